// round 4
// baseline (speedup 1.0000x reference)
#include <cuda_runtime.h>
#include <cstdint>
#include <cstddef>

typedef unsigned long long ull;

// ---------------------------------------------------------------------------
// Packed f32x2 helpers (SASS FFMA2 path — only reachable via explicit PTX)
// ---------------------------------------------------------------------------
__device__ __forceinline__ ull fma2(ull a, ull b, ull c) {
    ull d; asm("fma.rn.f32x2 %0,%1,%2,%3;" : "=l"(d) : "l"(a), "l"(b), "l"(c)); return d;
}
__device__ __forceinline__ ull mul2(ull a, ull b) {
    ull d; asm("mul.rn.f32x2 %0,%1,%2;" : "=l"(d) : "l"(a), "l"(b)); return d;
}
__device__ __forceinline__ ull pack2(float lo, float hi) {
    ull d; asm("mov.b64 %0,{%1,%2};" : "=l"(d) : "f"(lo), "f"(hi)); return d;
}
__device__ __forceinline__ ull dup2(float x) {
    ull d; asm("mov.b64 %0,{%1,%1};" : "=l"(d) : "f"(x)); return d;
}
__device__ __forceinline__ void unpack2(ull a, float& lo, float& hi) {
    asm("mov.b64 {%0,%1},%2;" : "=f"(lo), "=f"(hi) : "l"(a));
}
__device__ __forceinline__ ull neg2(ull a) { return a ^ 0x8000000080000000ULL; }

// ---------------------------------------------------------------------------
// Compile-time PGA(3,0,1) tables. Blade order matches the reference:
// idx : (), e0,e1,e2,e3, e01,e02,e03,e12,e13,e23, e012,e013,e023,e123, e0123
// ---------------------------------------------------------------------------
namespace ga {

__host__ __device__ constexpr unsigned bladeMask(int i) {
    constexpr unsigned m[16] = {0u,1u,2u,4u,8u, 3u,5u,9u,6u,10u,12u, 7u,11u,13u,14u, 15u};
    return m[i];
}
__host__ __device__ constexpr int idxOfMask(unsigned m) {
    constexpr int t[16] = {0,1,2,5,3,6,8,11,4,7,9,12,10,13,14,15};
    return t[m];
}
__host__ __device__ constexpr int invCnt(unsigned a, unsigned b) {
    int s = 0;
    for (int i = 0; i < 4; ++i)
        if ((b >> i) & 1u)
            for (int j = i + 1; j < 4; ++j)
                if ((a >> j) & 1u) ++s;
    return s;
}
__host__ __device__ constexpr float gpSign(int j, int k) {
    unsigned a = bladeMask(j), b = bladeMask(k);
    if (a & b & 1u) return 0.0f;                   // e0*e0 = 0
    return (invCnt(a, b) & 1) ? -1.0f : 1.0f;
}
__host__ __device__ constexpr int gpTgt(int j, int k) {
    return idxOfMask(bladeMask(j) ^ bladeMask(k));
}
__host__ __device__ constexpr float dSign(int t) {
    unsigned m = bladeMask(t);
    return (invCnt(m, 15u ^ m) & 1) ? -1.0f : 1.0f;
}
__host__ __device__ constexpr float jnCoef(int b, int c) {
    unsigned mb = bladeMask(b), mc = bladeMask(c);
    if ((mb | mc) != 15u) return 0.0f;
    unsigned ma = mb & mc;
    int ia = idxOfMask(15u ^ ma);
    unsigned cb = 15u ^ mb, cc = 15u ^ mc;
    float so = (invCnt(cb, cc) & 1) ? -1.0f : 1.0f;
    return dSign(ia) * so * dSign(b) * dSign(c);
}
__host__ __device__ constexpr int jnTgt(int b, int c) {
    return idxOfMask(bladeMask(b) & bladeMask(c));
}

template<int...> struct iseq {};
template<int N, int... S> struct mkseq : mkseq<N-1, N-1, S...> {};
template<int... S> struct mkseq<0, S...> { using type = iseq<S...>; };

template<int J, int K>
__device__ __forceinline__ void gpTerm(const ull (&L)[16], const ull (&nL)[16],
                                       const ull (&R)[16], ull (&h)[16]) {
    constexpr float s = gpSign(J, K);
    if constexpr (s > 0.5f) {
        constexpr int t = gpTgt(J, K);
        h[t] = fma2(L[J], R[K], h[t]);
    } else if constexpr (s < -0.5f) {
        constexpr int t = gpTgt(J, K);
        h[t] = fma2(nL[J], R[K], h[t]);
    }
}
template<int J, int... Ks>
__device__ __forceinline__ void gpRow(const ull (&L)[16], const ull (&nL)[16],
                                      const ull (&R)[16], ull (&h)[16], iseq<Ks...>) {
    (gpTerm<J, Ks>(L, nL, R, h), ...);
}
template<int... Js>
__device__ __forceinline__ void gpAll(const ull (&L)[16], const ull (&nL)[16],
                                      const ull (&R)[16], ull (&h)[16], iseq<Js...>) {
    (gpRow<Js>(L, nL, R, h, typename mkseq<16>::type{}), ...);
}

template<int J, int K>
__device__ __forceinline__ void jnTerm(const ull (&L)[16], const ull (&nL)[16],
                                       const ull (&R)[16], ull (&h)[16]) {
    constexpr float s = jnCoef(J, K);
    if constexpr (s > 0.5f) {
        constexpr int t = jnTgt(J, K);
        h[t] = fma2(L[J], R[K], h[t]);
    } else if constexpr (s < -0.5f) {
        constexpr int t = jnTgt(J, K);
        h[t] = fma2(nL[J], R[K], h[t]);
    }
}
template<int J, int... Ks>
__device__ __forceinline__ void jnRow(const ull (&L)[16], const ull (&nL)[16],
                                      const ull (&R)[16], ull (&h)[16], iseq<Ks...>) {
    (jnTerm<J, Ks>(L, nL, R, h), ...);
}
template<int... Js>
__device__ __forceinline__ void jnAll(const ull (&L)[16], const ull (&nL)[16],
                                      const ull (&R)[16], ull (&h)[16], iseq<Js...>) {
    (jnRow<Js>(L, nL, R, h, typename mkseq<16>::type{}), ...);
}

// Equivariant-linear accumulation (packed pair), one input channel.
// grades = [0,1,1,1,1, 2,2,2,2,2,2, 3,3,3,3, 4]
// e0 wedge (+1): 1<-0 (w5); 5,6,7<-2,3,4 (w6); 11,12,13<-8,9,10 (w7); 15<-14 (w8)
__device__ __forceinline__ void linAcc2(ull (&o)[16], const ull (&w)[9], const ull (&x)[16]) {
    o[0]  = fma2(w[0], x[0],  o[0]);
    o[1]  = fma2(w[1], x[1],  o[1]);  o[1]  = fma2(w[5], x[0],  o[1]);
    o[2]  = fma2(w[1], x[2],  o[2]);
    o[3]  = fma2(w[1], x[3],  o[3]);
    o[4]  = fma2(w[1], x[4],  o[4]);
    o[5]  = fma2(w[2], x[5],  o[5]);  o[5]  = fma2(w[6], x[2],  o[5]);
    o[6]  = fma2(w[2], x[6],  o[6]);  o[6]  = fma2(w[6], x[3],  o[6]);
    o[7]  = fma2(w[2], x[7],  o[7]);  o[7]  = fma2(w[6], x[4],  o[7]);
    o[8]  = fma2(w[2], x[8],  o[8]);
    o[9]  = fma2(w[2], x[9],  o[9]);
    o[10] = fma2(w[2], x[10], o[10]);
    o[11] = fma2(w[3], x[11], o[11]); o[11] = fma2(w[7], x[8],  o[11]);
    o[12] = fma2(w[3], x[12], o[12]); o[12] = fma2(w[7], x[9],  o[12]);
    o[13] = fma2(w[3], x[13], o[13]); o[13] = fma2(w[7], x[10], o[13]);
    o[14] = fma2(w[3], x[14], o[14]);
    o[15] = fma2(w[4], x[15], o[15]); o[15] = fma2(w[8], x[14], o[15]);
}

} // namespace ga

// ---------------------------------------------------------------------------
// Kernel
// ---------------------------------------------------------------------------
#define NW 8
#define NTHREADS (NW * 32)

// shared memory float offsets
#define OFF_WA    0        // [32 i][9 b][32 lane]
#define OFF_WB    9216
#define OFF_WO    18432    // [32 c][9 b][32 o]
#define OFF_SA    27648    // [64 s][32 lane]
#define OFF_SB    29696
#define OFF_S2MV  31744
#define OFF_WM1   33792    // [32 c][32 o]
#define OFF_WM2   34816
#define OFF_WS1   35840    // [64 s][32 o]
#define OFF_WS2   37888
#define OFF_STG   39936    // per-warp: xs2 1024 + sc2 128 + hs2 1024
#define STG_PER_WARP 2176
#define SMEM_FLOATS (OFF_STG + NW * STG_PER_WARP)
#define SMEM_BYTES  (SMEM_FLOATS * 4)

// swizzled offset (floats) of the 8-float pair-block (row r, quarter q);
// first float4 at off+sub, second at off+(sub^4)
__device__ __forceinline__ int swzOff(int r, int q) { return r * 32 + (((q ^ (r & 3))) << 3); }
__device__ __forceinline__ int swzSub(int r)        { return ((r >> 2) & 1) << 2; }

__global__ void __launch_bounds__(NTHREADS, 1)
gb_kernel(const float* __restrict__ mv,      // [ntok][32][16]
          const float* __restrict__ refmv,   // [ntok][16]
          const float* __restrict__ scal,    // [ntok][64]
          const float* __restrict__ wLmv, const float* __restrict__ wLs,
          const float* __restrict__ wRmv, const float* __restrict__ wRs,
          const float* __restrict__ wJLmv, const float* __restrict__ wJLs,
          const float* __restrict__ wJRmv, const float* __restrict__ wJRs,
          const float* __restrict__ wOmv,    // [32 o][32 c][9 b]
          const float* __restrict__ wS2mv,   // [32 o][64 s]
          const float* __restrict__ wMvs2s,  // [64 o][32 c]
          const float* __restrict__ wS2s,    // [64 o][64 s]
          float* __restrict__ out,           // [ntok][32][16]
          float* __restrict__ outS,          // [ntok][64]
          int ntok)
{
    extern __shared__ float sm[];
    float* WA   = sm + OFF_WA;
    float* WB   = sm + OFF_WB;
    float* WO   = sm + OFF_WO;
    float* SA   = sm + OFF_SA;
    float* SB   = sm + OFF_SB;
    float* S2MV = sm + OFF_S2MV;
    float* WM1  = sm + OFF_WM1;
    float* WM2  = sm + OFF_WM2;
    float* WS1  = sm + OFF_WS1;
    float* WS2  = sm + OFF_WS2;

    const int tid  = threadIdx.x;
    const int lane = tid & 31;
    const int wid  = tid >> 5;

    // ---- stage weights (lane-permuted) ----
    for (int idx = tid; idx < 9216; idx += NTHREADS) {
        const int l   = idx & 31;
        const int off = idx >> 5;               // i*9+b
        WA[idx] = (l < 16) ? wLmv[l * 288 + off] : wJLmv[(l - 16) * 288 + off];
        WB[idx] = (l < 16) ? wRmv[l * 288 + off] : wJRmv[(l - 16) * 288 + off];
        WO[idx] = wOmv[l * 288 + off];
    }
    for (int idx = tid; idx < 2048; idx += NTHREADS) {
        const int l = idx & 31;
        const int s = idx >> 5;
        SA[idx]   = (l < 16) ? wLs[l * 64 + s] : wJLs[(l - 16) * 64 + s];
        SB[idx]   = (l < 16) ? wRs[l * 64 + s] : wJRs[(l - 16) * 64 + s];
        S2MV[idx] = wS2mv[l * 64 + s];
        WS1[idx]  = wS2s[l * 64 + s];
        WS2[idx]  = wS2s[(32 + l) * 64 + s];
    }
    for (int idx = tid; idx < 1024; idx += NTHREADS) {
        const int l = idx & 31;
        const int c = idx >> 5;
        WM1[idx] = wMvs2s[l * 32 + c];
        WM2[idx] = wMvs2s[(32 + l) * 32 + c];
    }
    __syncthreads();

    float* xs = sm + OFF_STG + wid * STG_PER_WARP;  // 1024 floats: pair-interleaved x, swizzled
    float* sc = xs + 1024;                          // 128 floats: 64 scalar pairs
    float* hs = sc + 128;                           // 1024 floats: pair-interleaved hidden, swizzled

    const int gw = blockIdx.x * NW + wid;
    const int nw = gridDim.x * NW;
    const int npair = ntok >> 1;

    for (int p = gw; p < npair; p += nw) {
        const int tA = 2 * p, tB = 2 * p + 1;

        // ---- stage token-pair inputs (pair-interleaved, swizzled) ----
        const float4* gxA = reinterpret_cast<const float4*>(mv + (size_t)tA * 512);
        const float4* gxB = reinterpret_cast<const float4*>(mv + (size_t)tB * 512);
        #pragma unroll
        for (int it = 0; it < 4; ++it) {
            const int c = it * 32 + lane;        // chunk 0..127
            const int i = c >> 2, q = c & 3;
            const float4 a = gxA[c];
            const float4 b = gxB[c];
            const int off = swzOff(i, q), sub = swzSub(i);
            *reinterpret_cast<float4*>(xs + off + sub)       = make_float4(a.x, b.x, a.y, b.y);
            *reinterpret_cast<float4*>(xs + off + (sub ^ 4)) = make_float4(a.z, b.z, a.w, b.w);
        }
        {
            const float a0 = scal[(size_t)tA * 64 + lane];
            const float b0 = scal[(size_t)tB * 64 + lane];
            *reinterpret_cast<ull*>(sc + 2 * lane) = pack2(a0, b0);
            const float a1 = scal[(size_t)tA * 64 + 32 + lane];
            const float b1 = scal[(size_t)tB * 64 + 32 + lane];
            *reinterpret_cast<ull*>(sc + 2 * (32 + lane)) = pack2(a1, b1);
        }
        const ull refp = pack2(refmv[(size_t)tA * 16 + 15], refmv[(size_t)tB * 16 + 15]);
        __syncwarp();

        // ---- two input equi-linears owned by this lane (packed pair) ----
        ull A[16], Bv[16];
        #pragma unroll
        for (int j = 0; j < 16; ++j) { A[j] = 0ULL; Bv[j] = 0ULL; }

        #pragma unroll 8
        for (int s = 0; s < 64; ++s) {
            const ull sp = *reinterpret_cast<const ull*>(sc + 2 * s);
            A[0]  = fma2(dup2(SA[s * 32 + lane]), sp, A[0]);
            Bv[0] = fma2(dup2(SB[s * 32 + lane]), sp, Bv[0]);
        }

        #pragma unroll 4
        for (int i = 0; i < 32; ++i) {
            ull xr[16];
            #pragma unroll
            for (int q = 0; q < 4; ++q) {
                const int off = swzOff(i, q), sub = swzSub(i);
                const ulonglong2 p0 = *reinterpret_cast<const ulonglong2*>(xs + off + sub);
                const ulonglong2 p1 = *reinterpret_cast<const ulonglong2*>(xs + off + (sub ^ 4));
                xr[4*q+0] = p0.x; xr[4*q+1] = p0.y; xr[4*q+2] = p1.x; xr[4*q+3] = p1.y;
            }
            ull wa[9], wb[9];
            #pragma unroll
            for (int b = 0; b < 9; ++b) {
                wa[b] = dup2(WA[(i * 9 + b) * 32 + lane]);
                wb[b] = dup2(WB[(i * 9 + b) * 32 + lane]);
            }
            ga::linAcc2(A, wa, xr);
            ga::linAcc2(Bv, wb, xr);
        }

        // ---- bilinear: gp on lanes 0..15, join on lanes 16..31 ----
        ull h[16];
        #pragma unroll
        for (int j = 0; j < 16; ++j) h[j] = 0ULL;
        if (lane < 16) {
            ull nA[16];
            #pragma unroll
            for (int j = 0; j < 16; ++j) nA[j] = neg2(A[j]);
            ga::gpAll(A, nA, Bv, h, typename ga::mkseq<16>::type{});
        } else {
            ull nA[16];
            #pragma unroll
            for (int j = 0; j < 16; ++j) nA[j] = neg2(A[j]);
            ga::jnAll(A, nA, Bv, h, typename ga::mkseq<16>::type{});
            #pragma unroll
            for (int j = 0; j < 16; ++j) h[j] = mul2(h[j], refp);
        }
        // stage hidden (lane = channel c), swizzled pair layout
        #pragma unroll
        for (int q = 0; q < 4; ++q) {
            const int off = swzOff(lane, q), sub = swzSub(lane);
            *reinterpret_cast<ulonglong2*>(hs + off + sub)       = make_ulonglong2(h[4*q+0], h[4*q+1]);
            *reinterpret_cast<ulonglong2*>(hs + off + (sub ^ 4)) = make_ulonglong2(h[4*q+2], h[4*q+3]);
        }
        __syncwarp();

        // ---- output equi-linear: lane = output channel o ----
        ull O[16];
        #pragma unroll
        for (int j = 0; j < 16; ++j) O[j] = 0ULL;

        #pragma unroll 4
        for (int c = 0; c < 32; ++c) {
            ull hr[16];
            #pragma unroll
            for (int q = 0; q < 4; ++q) {
                const int off = swzOff(c, q), sub = swzSub(c);
                const ulonglong2 p0 = *reinterpret_cast<const ulonglong2*>(hs + off + sub);
                const ulonglong2 p1 = *reinterpret_cast<const ulonglong2*>(hs + off + (sub ^ 4));
                hr[4*q+0] = p0.x; hr[4*q+1] = p0.y; hr[4*q+2] = p1.x; hr[4*q+3] = p1.y;
            }
            ull wo[9];
            #pragma unroll
            for (int b = 0; b < 9; ++b) wo[b] = dup2(WO[(c * 9 + b) * 32 + lane]);
            ga::linAcc2(O, wo, hr);
        }
        #pragma unroll 8
        for (int s = 0; s < 64; ++s) {
            const ull sp = *reinterpret_cast<const ull*>(sc + 2 * s);
            O[0] = fma2(dup2(S2MV[s * 32 + lane]), sp, O[0]);
        }

        {
            float Oa[16], Ob[16];
            #pragma unroll
            for (int j = 0; j < 16; ++j) unpack2(O[j], Oa[j], Ob[j]);
            float* omA = out + (size_t)tA * 512 + lane * 16;
            float* omB = out + (size_t)tB * 512 + lane * 16;
            #pragma unroll
            for (int m = 0; m < 4; ++m) {
                *reinterpret_cast<float4*>(omA + m * 4) =
                    make_float4(Oa[m*4+0], Oa[m*4+1], Oa[m*4+2], Oa[m*4+3]);
                *reinterpret_cast<float4*>(omB + m * 4) =
                    make_float4(Ob[m*4+0], Ob[m*4+1], Ob[m*4+2], Ob[m*4+3]);
            }
        }

        // ---- scalar outputs ----
        ull os1 = 0ULL, os2 = 0ULL;
        #pragma unroll 4
        for (int c = 0; c < 32; ++c) {
            // pair of h[c][0]: first 8 bytes of block q=0
            const int off = swzOff(c, 0), sub = swzSub(c);
            const ull hv = *reinterpret_cast<const ull*>(hs + off + sub);
            os1 = fma2(dup2(WM1[c * 32 + lane]), hv, os1);
            os2 = fma2(dup2(WM2[c * 32 + lane]), hv, os2);
        }
        #pragma unroll 8
        for (int s = 0; s < 64; ++s) {
            const ull sp = *reinterpret_cast<const ull*>(sc + 2 * s);
            os1 = fma2(dup2(WS1[s * 32 + lane]), sp, os1);
            os2 = fma2(dup2(WS2[s * 32 + lane]), sp, os2);
        }
        {
            float a1, b1, a2, b2;
            unpack2(os1, a1, b1);
            unpack2(os2, a2, b2);
            outS[(size_t)tA * 64 + lane]      = a1;
            outS[(size_t)tA * 64 + 32 + lane] = a2;
            outS[(size_t)tB * 64 + lane]      = b1;
            outS[(size_t)tB * 64 + 32 + lane] = b2;
        }
        __syncwarp();   // staging reused next iteration
    }
}

// ---------------------------------------------------------------------------
// Launch
// ---------------------------------------------------------------------------
extern "C" void kernel_launch(void* const* d_in, const int* in_sizes, int n_in,
                              void* d_out, int out_size) {
    const float* mv     = (const float*)d_in[0];
    const float* refmv  = (const float*)d_in[1];
    const float* scal   = (const float*)d_in[2];
    // d_in[3..5] = basis, gp, jn (structure hardcoded at compile time)
    const float* wLmv   = (const float*)d_in[6];
    const float* wLs    = (const float*)d_in[7];
    const float* wRmv   = (const float*)d_in[8];
    const float* wRs    = (const float*)d_in[9];
    const float* wJLmv  = (const float*)d_in[10];
    const float* wJLs   = (const float*)d_in[11];
    const float* wJRmv  = (const float*)d_in[12];
    const float* wJRs   = (const float*)d_in[13];
    const float* wOmv   = (const float*)d_in[14];
    const float* wS2mv  = (const float*)d_in[15];
    const float* wMvs2s = (const float*)d_in[16];
    const float* wS2s   = (const float*)d_in[17];

    const int ntok = in_sizes[0] / 512;          // 32768
    float* out  = (float*)d_out;                 // [ntok*512] out_mv
    float* outS = out + (size_t)ntok * 512;      // [ntok*64]  out_s

    int dev = 0;
    cudaGetDevice(&dev);
    int nsm = 148;
    cudaDeviceGetAttribute(&nsm, cudaDevAttrMultiProcessorCount, dev);

    cudaFuncSetAttribute(gb_kernel, cudaFuncAttributeMaxDynamicSharedMemorySize, SMEM_BYTES);

    gb_kernel<<<nsm, NTHREADS, SMEM_BYTES>>>(
        mv, refmv, scal,
        wLmv, wLs, wRmv, wRs, wJLmv, wJLs, wJRmv, wJRs,
        wOmv, wS2mv, wMvs2s, wS2s,
        out, outS, ntok);
}

// round 5
// speedup vs baseline: 1.7717x; 1.7717x over previous
#include <cuda_runtime.h>
#include <cstdint>
#include <cstddef>

typedef unsigned long long ull;

// ---------------------------------------------------------------------------
// Packed f32x2 helpers (SASS FFMA2 path — only reachable via explicit PTX)
// ---------------------------------------------------------------------------
__device__ __forceinline__ ull fma2(ull a, ull b, ull c) {
    ull d; asm("fma.rn.f32x2 %0,%1,%2,%3;" : "=l"(d) : "l"(a), "l"(b), "l"(c)); return d;
}
__device__ __forceinline__ ull mul2(ull a, ull b) {
    ull d; asm("mul.rn.f32x2 %0,%1,%2;" : "=l"(d) : "l"(a), "l"(b)); return d;
}
__device__ __forceinline__ ull pack2(float lo, float hi) {
    ull d; asm("mov.b64 %0,{%1,%2};" : "=l"(d) : "f"(lo), "f"(hi)); return d;
}
__device__ __forceinline__ ull dup2(float x) {
    ull d; asm("mov.b64 %0,{%1,%1};" : "=l"(d) : "f"(x)); return d;
}
__device__ __forceinline__ void unpack2(ull a, float& lo, float& hi) {
    asm("mov.b64 {%0,%1},%2;" : "=f"(lo), "=f"(hi) : "l"(a));
}
__device__ __forceinline__ ull neg2(ull a) { return a ^ 0x8000000080000000ULL; }

// ---------------------------------------------------------------------------
// Compile-time PGA(3,0,1) tables. Blade order matches the reference:
// idx : (), e0,e1,e2,e3, e01,e02,e03,e12,e13,e23, e012,e013,e023,e123, e0123
// ---------------------------------------------------------------------------
namespace ga {

__host__ __device__ constexpr unsigned bladeMask(int i) {
    constexpr unsigned m[16] = {0u,1u,2u,4u,8u, 3u,5u,9u,6u,10u,12u, 7u,11u,13u,14u, 15u};
    return m[i];
}
__host__ __device__ constexpr int idxOfMask(unsigned m) {
    constexpr int t[16] = {0,1,2,5,3,6,8,11,4,7,9,12,10,13,14,15};
    return t[m];
}
__host__ __device__ constexpr int invCnt(unsigned a, unsigned b) {
    int s = 0;
    for (int i = 0; i < 4; ++i)
        if ((b >> i) & 1u)
            for (int j = i + 1; j < 4; ++j)
                if ((a >> j) & 1u) ++s;
    return s;
}
__host__ __device__ constexpr float gpSign(int j, int k) {
    unsigned a = bladeMask(j), b = bladeMask(k);
    if (a & b & 1u) return 0.0f;                   // e0*e0 = 0
    return (invCnt(a, b) & 1) ? -1.0f : 1.0f;
}
__host__ __device__ constexpr int gpTgt(int j, int k) {
    return idxOfMask(bladeMask(j) ^ bladeMask(k));
}
__host__ __device__ constexpr float dSign(int t) {
    unsigned m = bladeMask(t);
    return (invCnt(m, 15u ^ m) & 1) ? -1.0f : 1.0f;
}
__host__ __device__ constexpr float jnCoef(int b, int c) {
    unsigned mb = bladeMask(b), mc = bladeMask(c);
    if ((mb | mc) != 15u) return 0.0f;
    unsigned ma = mb & mc;
    int ia = idxOfMask(15u ^ ma);
    unsigned cb = 15u ^ mb, cc = 15u ^ mc;
    float so = (invCnt(cb, cc) & 1) ? -1.0f : 1.0f;
    return dSign(ia) * so * dSign(b) * dSign(c);
}
__host__ __device__ constexpr int jnTgt(int b, int c) {
    return idxOfMask(bladeMask(b) & bladeMask(c));
}

template<int...> struct iseq {};
template<int N, int... S> struct mkseq : mkseq<N-1, N-1, S...> {};
template<int... S> struct mkseq<0, S...> { using type = iseq<S...>; };

template<int J, int K>
__device__ __forceinline__ void gpTerm(const ull (&L)[16], const ull (&nL)[16],
                                       const ull (&R)[16], ull (&h)[16]) {
    constexpr float s = gpSign(J, K);
    if constexpr (s > 0.5f) {
        constexpr int t = gpTgt(J, K);
        h[t] = fma2(L[J], R[K], h[t]);
    } else if constexpr (s < -0.5f) {
        constexpr int t = gpTgt(J, K);
        h[t] = fma2(nL[J], R[K], h[t]);
    }
}
template<int J, int... Ks>
__device__ __forceinline__ void gpRow(const ull (&L)[16], const ull (&nL)[16],
                                      const ull (&R)[16], ull (&h)[16], iseq<Ks...>) {
    (gpTerm<J, Ks>(L, nL, R, h), ...);
}
template<int... Js>
__device__ __forceinline__ void gpAll(const ull (&L)[16], const ull (&nL)[16],
                                      const ull (&R)[16], ull (&h)[16], iseq<Js...>) {
    (gpRow<Js>(L, nL, R, h, typename mkseq<16>::type{}), ...);
}

template<int J, int K>
__device__ __forceinline__ void jnTerm(const ull (&L)[16], const ull (&nL)[16],
                                       const ull (&R)[16], ull (&h)[16]) {
    constexpr float s = jnCoef(J, K);
    if constexpr (s > 0.5f) {
        constexpr int t = jnTgt(J, K);
        h[t] = fma2(L[J], R[K], h[t]);
    } else if constexpr (s < -0.5f) {
        constexpr int t = jnTgt(J, K);
        h[t] = fma2(nL[J], R[K], h[t]);
    }
}
template<int J, int... Ks>
__device__ __forceinline__ void jnRow(const ull (&L)[16], const ull (&nL)[16],
                                      const ull (&R)[16], ull (&h)[16], iseq<Ks...>) {
    (jnTerm<J, Ks>(L, nL, R, h), ...);
}
template<int... Js>
__device__ __forceinline__ void jnAll(const ull (&L)[16], const ull (&nL)[16],
                                      const ull (&R)[16], ull (&h)[16], iseq<Js...>) {
    (jnRow<Js>(L, nL, R, h, typename mkseq<16>::type{}), ...);
}

// Equivariant-linear accumulation (packed pair), one input channel.
// grades = [0,1,1,1,1, 2,2,2,2,2,2, 3,3,3,3, 4]
// e0 wedge (+1): 1<-0 (w5); 5,6,7<-2,3,4 (w6); 11,12,13<-8,9,10 (w7); 15<-14 (w8)
__device__ __forceinline__ void linAcc2(ull (&o)[16], const ull (&w)[9], const ull (&x)[16]) {
    o[0]  = fma2(w[0], x[0],  o[0]);
    o[1]  = fma2(w[1], x[1],  o[1]);  o[1]  = fma2(w[5], x[0],  o[1]);
    o[2]  = fma2(w[1], x[2],  o[2]);
    o[3]  = fma2(w[1], x[3],  o[3]);
    o[4]  = fma2(w[1], x[4],  o[4]);
    o[5]  = fma2(w[2], x[5],  o[5]);  o[5]  = fma2(w[6], x[2],  o[5]);
    o[6]  = fma2(w[2], x[6],  o[6]);  o[6]  = fma2(w[6], x[3],  o[6]);
    o[7]  = fma2(w[2], x[7],  o[7]);  o[7]  = fma2(w[6], x[4],  o[7]);
    o[8]  = fma2(w[2], x[8],  o[8]);
    o[9]  = fma2(w[2], x[9],  o[9]);
    o[10] = fma2(w[2], x[10], o[10]);
    o[11] = fma2(w[3], x[11], o[11]); o[11] = fma2(w[7], x[8],  o[11]);
    o[12] = fma2(w[3], x[12], o[12]); o[12] = fma2(w[7], x[9],  o[12]);
    o[13] = fma2(w[3], x[13], o[13]); o[13] = fma2(w[7], x[10], o[13]);
    o[14] = fma2(w[3], x[14], o[14]);
    o[15] = fma2(w[4], x[15], o[15]); o[15] = fma2(w[8], x[14], o[15]);
}

} // namespace ga

// ---------------------------------------------------------------------------
// Kernel
// ---------------------------------------------------------------------------
#define NW 12
#define NTHREADS (NW * 32)

// shared memory float offsets
#define OFF_WA    0        // [32 i][9 b][32 lane]
#define OFF_WB    9216
#define OFF_WO    18432    // [32 c][9 b][32 o]
#define OFF_SA    27648    // [64 s][32 lane]
#define OFF_SB    29696
#define OFF_S2MV  31744
#define OFF_WM1   33792    // [32 c][32 o]
#define OFF_WM2   34816
#define OFF_WS1   35840    // [64 s][32 o]
#define OFF_WS2   37888
#define OFF_STG   39936
// Per-warp staging: one 1152-float buffer (32 rows x 36 floats) reused for
// pair-interleaved x THEN pair-interleaved hidden, + 128 floats scalar pairs.
#define ROWF 36
#define STG_PER_WARP (32 * ROWF + 128)     // 1280 floats
#define SMEM_FLOATS (OFF_STG + NW * STG_PER_WARP)
#define SMEM_BYTES  (SMEM_FLOATS * 4)      // 221,184 B

__global__ void __launch_bounds__(NTHREADS, 1)
gb_kernel(const float* __restrict__ mv,      // [ntok][32][16]
          const float* __restrict__ refmv,   // [ntok][16]
          const float* __restrict__ scal,    // [ntok][64]
          const float* __restrict__ wLmv, const float* __restrict__ wLs,
          const float* __restrict__ wRmv, const float* __restrict__ wRs,
          const float* __restrict__ wJLmv, const float* __restrict__ wJLs,
          const float* __restrict__ wJRmv, const float* __restrict__ wJRs,
          const float* __restrict__ wOmv,    // [32 o][32 c][9 b]
          const float* __restrict__ wS2mv,   // [32 o][64 s]
          const float* __restrict__ wMvs2s,  // [64 o][32 c]
          const float* __restrict__ wS2s,    // [64 o][64 s]
          float* __restrict__ out,           // [ntok][32][16]
          float* __restrict__ outS,          // [ntok][64]
          int ntok)
{
    extern __shared__ float sm[];
    float* WA   = sm + OFF_WA;
    float* WB   = sm + OFF_WB;
    float* WO   = sm + OFF_WO;
    float* SA   = sm + OFF_SA;
    float* SB   = sm + OFF_SB;
    float* S2MV = sm + OFF_S2MV;
    float* WM1  = sm + OFF_WM1;
    float* WM2  = sm + OFF_WM2;
    float* WS1  = sm + OFF_WS1;
    float* WS2  = sm + OFF_WS2;

    const int tid  = threadIdx.x;
    const int lane = tid & 31;
    const int wid  = tid >> 5;

    // ---- stage weights (lane-permuted) ----
    // lane<16: A=left[lane], B=right[lane];  lane>=16: A=jl[l-16], B=jr[l-16]
    for (int idx = tid; idx < 9216; idx += NTHREADS) {
        const int l   = idx & 31;
        const int off = idx >> 5;               // i*9+b
        WA[idx] = (l < 16) ? wLmv[l * 288 + off] : wJLmv[(l - 16) * 288 + off];
        WB[idx] = (l < 16) ? wRmv[l * 288 + off] : wJRmv[(l - 16) * 288 + off];
        WO[idx] = wOmv[l * 288 + off];
    }
    for (int idx = tid; idx < 2048; idx += NTHREADS) {
        const int l = idx & 31;
        const int s = idx >> 5;
        SA[idx]   = (l < 16) ? wLs[l * 64 + s] : wJLs[(l - 16) * 64 + s];
        SB[idx]   = (l < 16) ? wRs[l * 64 + s] : wJRs[(l - 16) * 64 + s];
        S2MV[idx] = wS2mv[l * 64 + s];
        WS1[idx]  = wS2s[l * 64 + s];
        WS2[idx]  = wS2s[(32 + l) * 64 + s];
    }
    for (int idx = tid; idx < 1024; idx += NTHREADS) {
        const int l = idx & 31;
        const int c = idx >> 5;
        WM1[idx] = wMvs2s[l * 32 + c];
        WM2[idx] = wMvs2s[(32 + l) * 32 + c];
    }
    __syncthreads();

    float* buf = sm + OFF_STG + wid * STG_PER_WARP; // 32 x 36 floats: xs, then hs
    float* sc  = buf + 32 * ROWF;                   // 128 floats: 64 scalar pairs

    const int gw = blockIdx.x * NW + wid;
    const int nw = gridDim.x * NW;
    const int npair = ntok >> 1;

    for (int p = gw; p < npair; p += nw) {
        const int tA = 2 * p, tB = 2 * p + 1;

        // ---- stage token-pair inputs (pair-interleaved rows of 36 floats) ----
        const float4* gxA = reinterpret_cast<const float4*>(mv + (size_t)tA * 512);
        const float4* gxB = reinterpret_cast<const float4*>(mv + (size_t)tB * 512);
        #pragma unroll
        for (int it = 0; it < 4; ++it) {
            const int c = it * 32 + lane;        // chunk 0..127
            const int i = c >> 2, q = c & 3;     // channel, quarter (blades 4q..4q+3)
            const float4 a = gxA[c];
            const float4 b = gxB[c];
            float* base = buf + i * ROWF + q * 8;
            *reinterpret_cast<float4*>(base)     = make_float4(a.x, b.x, a.y, b.y);
            *reinterpret_cast<float4*>(base + 4) = make_float4(a.z, b.z, a.w, b.w);
        }
        {
            const float a0 = scal[(size_t)tA * 64 + lane];
            const float b0 = scal[(size_t)tB * 64 + lane];
            *reinterpret_cast<ull*>(sc + 2 * lane) = pack2(a0, b0);
            const float a1 = scal[(size_t)tA * 64 + 32 + lane];
            const float b1 = scal[(size_t)tB * 64 + 32 + lane];
            *reinterpret_cast<ull*>(sc + 2 * (32 + lane)) = pack2(a1, b1);
        }
        const ull refp = pack2(refmv[(size_t)tA * 16 + 15], refmv[(size_t)tB * 16 + 15]);
        __syncwarp();

        // ---- two input equi-linears owned by this lane (packed pair) ----
        ull A[16], Bv[16];
        #pragma unroll
        for (int j = 0; j < 16; ++j) { A[j] = 0ULL; Bv[j] = 0ULL; }

        #pragma unroll 8
        for (int s = 0; s < 64; ++s) {
            const ull sp = *reinterpret_cast<const ull*>(sc + 2 * s);
            A[0]  = fma2(dup2(SA[s * 32 + lane]), sp, A[0]);
            Bv[0] = fma2(dup2(SB[s * 32 + lane]), sp, Bv[0]);
        }

        #pragma unroll 4
        for (int i = 0; i < 32; ++i) {
            ull xr[16];
            const ulonglong2* xp = reinterpret_cast<const ulonglong2*>(buf + i * ROWF);
            #pragma unroll
            for (int t = 0; t < 8; ++t) {        // broadcast reads: conflict-free
                const ulonglong2 v = xp[t];
                xr[2*t] = v.x; xr[2*t+1] = v.y;
            }
            ull wa[9], wb[9];
            #pragma unroll
            for (int b = 0; b < 9; ++b) {
                wa[b] = dup2(WA[(i * 9 + b) * 32 + lane]);
                wb[b] = dup2(WB[(i * 9 + b) * 32 + lane]);
            }
            ga::linAcc2(A, wa, xr);
            ga::linAcc2(Bv, wb, xr);
        }
        __syncwarp();   // all lanes done reading x staging

        // ---- bilinear: gp on lanes 0..15, join on lanes 16..31 ----
        ull h[16];
        #pragma unroll
        for (int j = 0; j < 16; ++j) h[j] = 0ULL;
        {
            ull nA[16];
            #pragma unroll
            for (int j = 0; j < 16; ++j) nA[j] = neg2(A[j]);
            if (lane < 16) {
                ga::gpAll(A, nA, Bv, h, typename ga::mkseq<16>::type{});
            } else {
                ga::jnAll(A, nA, Bv, h, typename ga::mkseq<16>::type{});
                #pragma unroll
                for (int j = 0; j < 16; ++j) h[j] = mul2(h[j], refp);
            }
        }
        // stage hidden (lane = channel c) into the SAME buffer
        {
            ulonglong2* hp = reinterpret_cast<ulonglong2*>(buf + lane * ROWF);
            #pragma unroll
            for (int t = 0; t < 8; ++t) hp[t] = make_ulonglong2(h[2*t], h[2*t+1]);
        }
        __syncwarp();

        // ---- output equi-linear: lane = output channel o ----
        ull O[16];
        #pragma unroll
        for (int j = 0; j < 16; ++j) O[j] = 0ULL;

        #pragma unroll 4
        for (int c = 0; c < 32; ++c) {
            ull hr[16];
            const ulonglong2* hp = reinterpret_cast<const ulonglong2*>(buf + c * ROWF);
            #pragma unroll
            for (int t = 0; t < 8; ++t) {        // broadcast reads
                const ulonglong2 v = hp[t];
                hr[2*t] = v.x; hr[2*t+1] = v.y;
            }
            ull wo[9];
            #pragma unroll
            for (int b = 0; b < 9; ++b) wo[b] = dup2(WO[(c * 9 + b) * 32 + lane]);
            ga::linAcc2(O, wo, hr);
        }
        #pragma unroll 8
        for (int s = 0; s < 64; ++s) {
            const ull sp = *reinterpret_cast<const ull*>(sc + 2 * s);
            O[0] = fma2(dup2(S2MV[s * 32 + lane]), sp, O[0]);
        }

        {
            float Oa[16], Ob[16];
            #pragma unroll
            for (int j = 0; j < 16; ++j) unpack2(O[j], Oa[j], Ob[j]);
            float* omA = out + (size_t)tA * 512 + lane * 16;
            float* omB = out + (size_t)tB * 512 + lane * 16;
            #pragma unroll
            for (int m = 0; m < 4; ++m) {
                *reinterpret_cast<float4*>(omA + m * 4) =
                    make_float4(Oa[m*4+0], Oa[m*4+1], Oa[m*4+2], Oa[m*4+3]);
                *reinterpret_cast<float4*>(omB + m * 4) =
                    make_float4(Ob[m*4+0], Ob[m*4+1], Ob[m*4+2], Ob[m*4+3]);
            }
        }

        // ---- scalar outputs ----
        ull os1 = 0ULL, os2 = 0ULL;
        #pragma unroll 4
        for (int c = 0; c < 32; ++c) {
            const ull hv = *reinterpret_cast<const ull*>(buf + c * ROWF); // h[c][0] pair
            os1 = fma2(dup2(WM1[c * 32 + lane]), hv, os1);
            os2 = fma2(dup2(WM2[c * 32 + lane]), hv, os2);
        }
        #pragma unroll 8
        for (int s = 0; s < 64; ++s) {
            const ull sp = *reinterpret_cast<const ull*>(sc + 2 * s);
            os1 = fma2(dup2(WS1[s * 32 + lane]), sp, os1);
            os2 = fma2(dup2(WS2[s * 32 + lane]), sp, os2);
        }
        {
            float a1, b1, a2, b2;
            unpack2(os1, a1, b1);
            unpack2(os2, a2, b2);
            outS[(size_t)tA * 64 + lane]      = a1;
            outS[(size_t)tA * 64 + 32 + lane] = a2;
            outS[(size_t)tB * 64 + lane]      = b1;
            outS[(size_t)tB * 64 + 32 + lane] = b2;
        }
        __syncwarp();   // staging reused next iteration
    }
}

// ---------------------------------------------------------------------------
// Launch
// ---------------------------------------------------------------------------
extern "C" void kernel_launch(void* const* d_in, const int* in_sizes, int n_in,
                              void* d_out, int out_size) {
    const float* mv     = (const float*)d_in[0];
    const float* refmv  = (const float*)d_in[1];
    const float* scal   = (const float*)d_in[2];
    // d_in[3..5] = basis, gp, jn (structure hardcoded at compile time)
    const float* wLmv   = (const float*)d_in[6];
    const float* wLs    = (const float*)d_in[7];
    const float* wRmv   = (const float*)d_in[8];
    const float* wRs    = (const float*)d_in[9];
    const float* wJLmv  = (const float*)d_in[10];
    const float* wJLs   = (const float*)d_in[11];
    const float* wJRmv  = (const float*)d_in[12];
    const float* wJRs   = (const float*)d_in[13];
    const float* wOmv   = (const float*)d_in[14];
    const float* wS2mv  = (const float*)d_in[15];
    const float* wMvs2s = (const float*)d_in[16];
    const float* wS2s   = (const float*)d_in[17];

    const int ntok = in_sizes[0] / 512;          // 32768
    float* out  = (float*)d_out;                 // [ntok*512] out_mv
    float* outS = out + (size_t)ntok * 512;      // [ntok*64]  out_s

    int dev = 0;
    cudaGetDevice(&dev);
    int nsm = 148;
    cudaDeviceGetAttribute(&nsm, cudaDevAttrMultiProcessorCount, dev);

    cudaFuncSetAttribute(gb_kernel, cudaFuncAttributeMaxDynamicSharedMemorySize, SMEM_BYTES);

    gb_kernel<<<nsm, NTHREADS, SMEM_BYTES>>>(
        mv, refmv, scal,
        wLmv, wLs, wRmv, wRs, wJLmv, wJLs, wJRmv, wJRs,
        wOmv, wS2mv, wMvs2s, wS2s,
        out, outS, ntok);
}

// round 6
// speedup vs baseline: 1.8826x; 1.0626x over previous
#include <cuda_runtime.h>
#include <cstdint>
#include <cstddef>

typedef unsigned long long ull;

// ---------------------------------------------------------------------------
// Packed f32x2 helpers (SASS FFMA2 path — only reachable via explicit PTX)
// ---------------------------------------------------------------------------
__device__ __forceinline__ ull fma2(ull a, ull b, ull c) {
    ull d; asm("fma.rn.f32x2 %0,%1,%2,%3;" : "=l"(d) : "l"(a), "l"(b), "l"(c)); return d;
}
__device__ __forceinline__ ull mul2(ull a, ull b) {
    ull d; asm("mul.rn.f32x2 %0,%1,%2;" : "=l"(d) : "l"(a), "l"(b)); return d;
}
__device__ __forceinline__ ull pack2(float lo, float hi) {
    ull d; asm("mov.b64 %0,{%1,%2};" : "=l"(d) : "f"(lo), "f"(hi)); return d;
}
__device__ __forceinline__ ull dup2(float x) {
    ull d; asm("mov.b64 %0,{%1,%1};" : "=l"(d) : "f"(x)); return d;
}
__device__ __forceinline__ void unpack2(ull a, float& lo, float& hi) {
    asm("mov.b64 {%0,%1},%2;" : "=f"(lo), "=f"(hi) : "l"(a));
}
__device__ __forceinline__ ull neg2(ull a) { return a ^ 0x8000000080000000ULL; }

// ---------------------------------------------------------------------------
// Compile-time PGA(3,0,1) tables. Blade order matches the reference:
// idx : (), e0,e1,e2,e3, e01,e02,e03,e12,e13,e23, e012,e013,e023,e123, e0123
// ---------------------------------------------------------------------------
namespace ga {

__host__ __device__ constexpr unsigned bladeMask(int i) {
    constexpr unsigned m[16] = {0u,1u,2u,4u,8u, 3u,5u,9u,6u,10u,12u, 7u,11u,13u,14u, 15u};
    return m[i];
}
__host__ __device__ constexpr int idxOfMask(unsigned m) {
    constexpr int t[16] = {0,1,2,5,3,6,8,11,4,7,9,12,10,13,14,15};
    return t[m];
}
__host__ __device__ constexpr int invCnt(unsigned a, unsigned b) {
    int s = 0;
    for (int i = 0; i < 4; ++i)
        if ((b >> i) & 1u)
            for (int j = i + 1; j < 4; ++j)
                if ((a >> j) & 1u) ++s;
    return s;
}
__host__ __device__ constexpr float gpSign(int j, int k) {
    unsigned a = bladeMask(j), b = bladeMask(k);
    if (a & b & 1u) return 0.0f;                   // e0*e0 = 0
    return (invCnt(a, b) & 1) ? -1.0f : 1.0f;
}
__host__ __device__ constexpr int gpTgt(int j, int k) {
    return idxOfMask(bladeMask(j) ^ bladeMask(k));
}
__host__ __device__ constexpr float dSign(int t) {
    unsigned m = bladeMask(t);
    return (invCnt(m, 15u ^ m) & 1) ? -1.0f : 1.0f;
}
__host__ __device__ constexpr float jnCoef(int b, int c) {
    unsigned mb = bladeMask(b), mc = bladeMask(c);
    if ((mb | mc) != 15u) return 0.0f;
    unsigned ma = mb & mc;
    int ia = idxOfMask(15u ^ ma);
    unsigned cb = 15u ^ mb, cc = 15u ^ mc;
    float so = (invCnt(cb, cc) & 1) ? -1.0f : 1.0f;
    return dSign(ia) * so * dSign(b) * dSign(c);
}
__host__ __device__ constexpr int jnTgt(int b, int c) {
    return idxOfMask(bladeMask(b) & bladeMask(c));
}

template<int...> struct iseq {};
template<int N, int... S> struct mkseq : mkseq<N-1, N-1, S...> {};
template<int... S> struct mkseq<0, S...> { using type = iseq<S...>; };

template<int J, int K>
__device__ __forceinline__ void gpTerm(const ull (&L)[16], const ull (&nL)[16],
                                       const ull (&R)[16], ull (&h)[16]) {
    constexpr float s = gpSign(J, K);
    if constexpr (s > 0.5f) {
        constexpr int t = gpTgt(J, K);
        h[t] = fma2(L[J], R[K], h[t]);
    } else if constexpr (s < -0.5f) {
        constexpr int t = gpTgt(J, K);
        h[t] = fma2(nL[J], R[K], h[t]);
    }
}
template<int J, int... Ks>
__device__ __forceinline__ void gpRow(const ull (&L)[16], const ull (&nL)[16],
                                      const ull (&R)[16], ull (&h)[16], iseq<Ks...>) {
    (gpTerm<J, Ks>(L, nL, R, h), ...);
}
template<int... Js>
__device__ __forceinline__ void gpAll(const ull (&L)[16], const ull (&nL)[16],
                                      const ull (&R)[16], ull (&h)[16], iseq<Js...>) {
    (gpRow<Js>(L, nL, R, h, typename mkseq<16>::type{}), ...);
}

template<int J, int K>
__device__ __forceinline__ void jnTerm(const ull (&L)[16], const ull (&nL)[16],
                                       const ull (&R)[16], ull (&h)[16]) {
    constexpr float s = jnCoef(J, K);
    if constexpr (s > 0.5f) {
        constexpr int t = jnTgt(J, K);
        h[t] = fma2(L[J], R[K], h[t]);
    } else if constexpr (s < -0.5f) {
        constexpr int t = jnTgt(J, K);
        h[t] = fma2(nL[J], R[K], h[t]);
    }
}
template<int J, int... Ks>
__device__ __forceinline__ void jnRow(const ull (&L)[16], const ull (&nL)[16],
                                      const ull (&R)[16], ull (&h)[16], iseq<Ks...>) {
    (jnTerm<J, Ks>(L, nL, R, h), ...);
}
template<int... Js>
__device__ __forceinline__ void jnAll(const ull (&L)[16], const ull (&nL)[16],
                                      const ull (&R)[16], ull (&h)[16], iseq<Js...>) {
    (jnRow<Js>(L, nL, R, h, typename mkseq<16>::type{}), ...);
}

// Equivariant-linear accumulation (packed pair), one input channel.
// grades = [0,1,1,1,1, 2,2,2,2,2,2, 3,3,3,3, 4]
// e0 wedge (+1): 1<-0 (w5); 5,6,7<-2,3,4 (w6); 11,12,13<-8,9,10 (w7); 15<-14 (w8)
__device__ __forceinline__ void linAcc2(ull (&o)[16], const ull (&w)[9], const ull (&x)[16]) {
    o[0]  = fma2(w[0], x[0],  o[0]);
    o[1]  = fma2(w[1], x[1],  o[1]);  o[1]  = fma2(w[5], x[0],  o[1]);
    o[2]  = fma2(w[1], x[2],  o[2]);
    o[3]  = fma2(w[1], x[3],  o[3]);
    o[4]  = fma2(w[1], x[4],  o[4]);
    o[5]  = fma2(w[2], x[5],  o[5]);  o[5]  = fma2(w[6], x[2],  o[5]);
    o[6]  = fma2(w[2], x[6],  o[6]);  o[6]  = fma2(w[6], x[3],  o[6]);
    o[7]  = fma2(w[2], x[7],  o[7]);  o[7]  = fma2(w[6], x[4],  o[7]);
    o[8]  = fma2(w[2], x[8],  o[8]);
    o[9]  = fma2(w[2], x[9],  o[9]);
    o[10] = fma2(w[2], x[10], o[10]);
    o[11] = fma2(w[3], x[11], o[11]); o[11] = fma2(w[7], x[8],  o[11]);
    o[12] = fma2(w[3], x[12], o[12]); o[12] = fma2(w[7], x[9],  o[12]);
    o[13] = fma2(w[3], x[13], o[13]); o[13] = fma2(w[7], x[10], o[13]);
    o[14] = fma2(w[3], x[14], o[14]);
    o[15] = fma2(w[4], x[15], o[15]); o[15] = fma2(w[8], x[14], o[15]);
}

} // namespace ga

// ---------------------------------------------------------------------------
// Kernel
// ---------------------------------------------------------------------------
#define NW 12
#define NTHREADS (NW * 32)

// shared memory float offsets
#define OFF_WA    0        // [32 i][9 b][32 lane]
#define OFF_WB    9216
#define OFF_WO    18432    // [32 c][9 b][32 o]
#define OFF_SA    27648    // [64 s][32 lane]
#define OFF_SB    29696
#define OFF_S2MV  31744
#define OFF_WM1   33792    // [32 c][32 o]
#define OFF_WM2   34816
#define OFF_WS1   35840    // [64 s][32 o]
#define OFF_WS2   37888
#define OFF_STG   39936
// Per-warp staging: 32 rows x 32 floats (XOR-swizzled ulonglong2 slots),
// reused for pair-interleaved x THEN hidden, + 128 floats scalar pairs.
#define STG_PER_WARP (32 * 32 + 128)       // 1152 floats
#define SMEM_FLOATS (OFF_STG + NW * STG_PER_WARP)
#define SMEM_BYTES  (SMEM_FLOATS * 4)      // 215,040 B

__global__ void __launch_bounds__(NTHREADS, 1)
gb_kernel(const float* __restrict__ mv,      // [ntok][32][16]
          const float* __restrict__ refmv,   // [ntok][16]
          const float* __restrict__ scal,    // [ntok][64]
          const float* __restrict__ wLmv, const float* __restrict__ wLs,
          const float* __restrict__ wRmv, const float* __restrict__ wRs,
          const float* __restrict__ wJLmv, const float* __restrict__ wJLs,
          const float* __restrict__ wJRmv, const float* __restrict__ wJRs,
          const float* __restrict__ wOmv,    // [32 o][32 c][9 b]
          const float* __restrict__ wS2mv,   // [32 o][64 s]
          const float* __restrict__ wMvs2s,  // [64 o][32 c]
          const float* __restrict__ wS2s,    // [64 o][64 s]
          float* __restrict__ out,           // [ntok][32][16]
          float* __restrict__ outS,          // [ntok][64]
          int ntok)
{
    extern __shared__ float sm[];
    float* WA   = sm + OFF_WA;
    float* WB   = sm + OFF_WB;
    float* WO   = sm + OFF_WO;
    float* SA   = sm + OFF_SA;
    float* SB   = sm + OFF_SB;
    float* S2MV = sm + OFF_S2MV;
    float* WM1  = sm + OFF_WM1;
    float* WM2  = sm + OFF_WM2;
    float* WS1  = sm + OFF_WS1;
    float* WS2  = sm + OFF_WS2;

    const int tid  = threadIdx.x;
    const int lane = tid & 31;
    const int wid  = tid >> 5;

    // ---- stage weights (lane-permuted) ----
    // lane<16: A=left[lane], B=right[lane];  lane>=16: A=jl[l-16], B=jr[l-16]
    for (int idx = tid; idx < 9216; idx += NTHREADS) {
        const int l   = idx & 31;
        const int off = idx >> 5;               // i*9+b
        WA[idx] = (l < 16) ? wLmv[l * 288 + off] : wJLmv[(l - 16) * 288 + off];
        WB[idx] = (l < 16) ? wRmv[l * 288 + off] : wJRmv[(l - 16) * 288 + off];
        WO[idx] = wOmv[l * 288 + off];
    }
    for (int idx = tid; idx < 2048; idx += NTHREADS) {
        const int l = idx & 31;
        const int s = idx >> 5;
        SA[idx]   = (l < 16) ? wLs[l * 64 + s] : wJLs[(l - 16) * 64 + s];
        SB[idx]   = (l < 16) ? wRs[l * 64 + s] : wJRs[(l - 16) * 64 + s];
        S2MV[idx] = wS2mv[l * 64 + s];
        WS1[idx]  = wS2s[l * 64 + s];
        WS2[idx]  = wS2s[(32 + l) * 64 + s];
    }
    for (int idx = tid; idx < 1024; idx += NTHREADS) {
        const int l = idx & 31;
        const int c = idx >> 5;
        WM1[idx] = wMvs2s[l * 32 + c];
        WM2[idx] = wMvs2s[(32 + l) * 32 + c];
    }
    __syncthreads();

    float* buf = sm + OFF_STG + wid * STG_PER_WARP; // 32 rows x 32 floats (swizzled)
    float* sc  = buf + 1024;                        // 128 floats: 64 scalar pairs

    const int gw = blockIdx.x * NW + wid;
    const int nw = gridDim.x * NW;
    const int npair = ntok >> 1;

    for (int p = gw; p < npair; p += nw) {
        const int tA = 2 * p, tB = 2 * p + 1;

        // ---- stage token-pair inputs ----
        // Row i (32 floats = 16 ull slots as 8 ulonglong2); logical ulonglong2
        // slot t holds blades (2t, 2t+1) pairs; physical slot = t ^ (i & 7).
        const float4* gxA = reinterpret_cast<const float4*>(mv + (size_t)tA * 512);
        const float4* gxB = reinterpret_cast<const float4*>(mv + (size_t)tB * 512);
        #pragma unroll
        for (int it = 0; it < 4; ++it) {
            const int c = it * 32 + lane;        // chunk 0..127
            const int i = c >> 2, q = c & 3;     // channel, quarter (blades 4q..4q+3)
            const float4 a = gxA[c];
            const float4 b = gxB[c];
            const int m  = i & 7;
            const int p0 = (2 * q) ^ m;          // slot for blades 4q,4q+1
            const int p1 = p0 ^ 1;               // slot for blades 4q+2,4q+3
            float* base = buf + i * 32;
            *reinterpret_cast<float4*>(base + p0 * 4) = make_float4(a.x, b.x, a.y, b.y);
            *reinterpret_cast<float4*>(base + p1 * 4) = make_float4(a.z, b.z, a.w, b.w);
        }
        {
            const float a0 = scal[(size_t)tA * 64 + lane];
            const float b0 = scal[(size_t)tB * 64 + lane];
            *reinterpret_cast<ull*>(sc + 2 * lane) = pack2(a0, b0);
            const float a1 = scal[(size_t)tA * 64 + 32 + lane];
            const float b1 = scal[(size_t)tB * 64 + 32 + lane];
            *reinterpret_cast<ull*>(sc + 2 * (32 + lane)) = pack2(a1, b1);
        }
        const ull refp = pack2(refmv[(size_t)tA * 16 + 15], refmv[(size_t)tB * 16 + 15]);
        __syncwarp();

        // ---- ONE merged pass over the scalar inputs:
        //      A[0], Bv[0] (input linears) + O0 (out mv) + os1/os2 (out s) ----
        ull A[16], Bv[16];
        #pragma unroll
        for (int j = 0; j < 16; ++j) { A[j] = 0ULL; Bv[j] = 0ULL; }
        ull O0 = 0ULL, os1 = 0ULL, os2 = 0ULL;

        #pragma unroll 8
        for (int s = 0; s < 64; ++s) {
            const ull sp = *reinterpret_cast<const ull*>(sc + 2 * s);
            A[0]  = fma2(dup2(SA[s * 32 + lane]),   sp, A[0]);
            Bv[0] = fma2(dup2(SB[s * 32 + lane]),   sp, Bv[0]);
            O0    = fma2(dup2(S2MV[s * 32 + lane]), sp, O0);
            os1   = fma2(dup2(WS1[s * 32 + lane]),  sp, os1);
            os2   = fma2(dup2(WS2[s * 32 + lane]),  sp, os2);
        }

        // ---- input equi-linears (i unrolled in groups of 8 => compile-time XOR) ----
        for (int i0 = 0; i0 < 32; i0 += 8) {
            #pragma unroll
            for (int k = 0; k < 8; ++k) {
                const int i = i0 + k;
                ull xr[16];
                const float* base = buf + i * 32;
                #pragma unroll
                for (int t = 0; t < 8; ++t) {    // broadcast reads, swizzled slots
                    const ulonglong2 v =
                        *reinterpret_cast<const ulonglong2*>(base + ((t ^ k) * 4));
                    xr[2*t] = v.x; xr[2*t+1] = v.y;
                }
                ull wa[9], wb[9];
                #pragma unroll
                for (int b = 0; b < 9; ++b) {
                    wa[b] = dup2(WA[(i * 9 + b) * 32 + lane]);
                    wb[b] = dup2(WB[(i * 9 + b) * 32 + lane]);
                }
                ga::linAcc2(A, wa, xr);
                ga::linAcc2(Bv, wb, xr);
            }
        }
        __syncwarp();   // all lanes done reading x staging

        // ---- bilinear: gp on lanes 0..15, join on lanes 16..31 ----
        ull h[16];
        #pragma unroll
        for (int j = 0; j < 16; ++j) h[j] = 0ULL;
        {
            ull nA[16];
            #pragma unroll
            for (int j = 0; j < 16; ++j) nA[j] = neg2(A[j]);
            if (lane < 16) {
                ga::gpAll(A, nA, Bv, h, typename ga::mkseq<16>::type{});
            } else {
                ga::jnAll(A, nA, Bv, h, typename ga::mkseq<16>::type{});
                #pragma unroll
                for (int j = 0; j < 16; ++j) h[j] = mul2(h[j], refp);
            }
        }
        // stage hidden (lane = channel) into the SAME buffer, swizzled
        {
            float* base = buf + lane * 32;
            const int m = lane & 7;
            #pragma unroll
            for (int t = 0; t < 8; ++t)
                *reinterpret_cast<ulonglong2*>(base + ((t ^ m) * 4)) =
                    make_ulonglong2(h[2*t], h[2*t+1]);
        }
        __syncwarp();

        // ---- output equi-linear: lane = output channel o ----
        ull O[16];
        O[0] = O0;
        #pragma unroll
        for (int j = 1; j < 16; ++j) O[j] = 0ULL;

        for (int c0 = 0; c0 < 32; c0 += 8) {
            #pragma unroll
            for (int k = 0; k < 8; ++k) {
                const int c = c0 + k;
                ull hr[16];
                const float* base = buf + c * 32;
                #pragma unroll
                for (int t = 0; t < 8; ++t) {    // broadcast reads, swizzled slots
                    const ulonglong2 v =
                        *reinterpret_cast<const ulonglong2*>(base + ((t ^ k) * 4));
                    hr[2*t] = v.x; hr[2*t+1] = v.y;
                }
                ull wo[9];
                #pragma unroll
                for (int b = 0; b < 9; ++b) wo[b] = dup2(WO[(c * 9 + b) * 32 + lane]);
                ga::linAcc2(O, wo, hr);

                // scalar head contribution from h[c][0] (first 8B of logical slot 0)
                const ull hv = *reinterpret_cast<const ull*>(base + (k * 4));
                os1 = fma2(dup2(WM1[c * 32 + lane]), hv, os1);
                os2 = fma2(dup2(WM2[c * 32 + lane]), hv, os2);
            }
        }

        {
            float Oa[16], Ob[16];
            #pragma unroll
            for (int j = 0; j < 16; ++j) unpack2(O[j], Oa[j], Ob[j]);
            float* omA = out + (size_t)tA * 512 + lane * 16;
            float* omB = out + (size_t)tB * 512 + lane * 16;
            #pragma unroll
            for (int m = 0; m < 4; ++m) {
                *reinterpret_cast<float4*>(omA + m * 4) =
                    make_float4(Oa[m*4+0], Oa[m*4+1], Oa[m*4+2], Oa[m*4+3]);
                *reinterpret_cast<float4*>(omB + m * 4) =
                    make_float4(Ob[m*4+0], Ob[m*4+1], Ob[m*4+2], Ob[m*4+3]);
            }
        }
        {
            float a1, b1, a2, b2;
            unpack2(os1, a1, b1);
            unpack2(os2, a2, b2);
            outS[(size_t)tA * 64 + lane]      = a1;
            outS[(size_t)tA * 64 + 32 + lane] = a2;
            outS[(size_t)tB * 64 + lane]      = b1;
            outS[(size_t)tB * 64 + 32 + lane] = b2;
        }
        __syncwarp();   // staging reused next iteration
    }
}

// ---------------------------------------------------------------------------
// Launch
// ---------------------------------------------------------------------------
extern "C" void kernel_launch(void* const* d_in, const int* in_sizes, int n_in,
                              void* d_out, int out_size) {
    const float* mv     = (const float*)d_in[0];
    const float* refmv  = (const float*)d_in[1];
    const float* scal   = (const float*)d_in[2];
    // d_in[3..5] = basis, gp, jn (structure hardcoded at compile time)
    const float* wLmv   = (const float*)d_in[6];
    const float* wLs    = (const float*)d_in[7];
    const float* wRmv   = (const float*)d_in[8];
    const float* wRs    = (const float*)d_in[9];
    const float* wJLmv  = (const float*)d_in[10];
    const float* wJLs   = (const float*)d_in[11];
    const float* wJRmv  = (const float*)d_in[12];
    const float* wJRs   = (const float*)d_in[13];
    const float* wOmv   = (const float*)d_in[14];
    const float* wS2mv  = (const float*)d_in[15];
    const float* wMvs2s = (const float*)d_in[16];
    const float* wS2s   = (const float*)d_in[17];

    const int ntok = in_sizes[0] / 512;          // 32768
    float* out  = (float*)d_out;                 // [ntok*512] out_mv
    float* outS = out + (size_t)ntok * 512;      // [ntok*64]  out_s

    int dev = 0;
    cudaGetDevice(&dev);
    int nsm = 148;
    cudaDeviceGetAttribute(&nsm, cudaDevAttrMultiProcessorCount, dev);

    cudaFuncSetAttribute(gb_kernel, cudaFuncAttributeMaxDynamicSharedMemorySize, SMEM_BYTES);

    gb_kernel<<<nsm, NTHREADS, SMEM_BYTES>>>(
        mv, refmv, scal,
        wLmv, wLs, wRmv, wRs, wJLmv, wJLs, wJRmv, wJRs,
        wOmv, wS2mv, wMvs2s, wS2s,
        out, outS, ntok);
}

// round 7
// speedup vs baseline: 1.8856x; 1.0016x over previous
#include <cuda_runtime.h>
#include <cstdint>
#include <cstddef>

typedef unsigned long long ull;

// ---------------------------------------------------------------------------
// Packed f32x2 helpers (SASS FFMA2 path — only reachable via explicit PTX)
// ---------------------------------------------------------------------------
__device__ __forceinline__ ull fma2(ull a, ull b, ull c) {
    ull d; asm("fma.rn.f32x2 %0,%1,%2,%3;" : "=l"(d) : "l"(a), "l"(b), "l"(c)); return d;
}
__device__ __forceinline__ ull mul2(ull a, ull b) {
    ull d; asm("mul.rn.f32x2 %0,%1,%2;" : "=l"(d) : "l"(a), "l"(b)); return d;
}
__device__ __forceinline__ ull pack2(float lo, float hi) {
    ull d; asm("mov.b64 %0,{%1,%2};" : "=l"(d) : "f"(lo), "f"(hi)); return d;
}
__device__ __forceinline__ ull dup2(float x) {
    ull d; asm("mov.b64 %0,{%1,%1};" : "=l"(d) : "f"(x)); return d;
}
__device__ __forceinline__ void unpack2(ull a, float& lo, float& hi) {
    asm("mov.b64 {%0,%1},%2;" : "=f"(lo), "=f"(hi) : "l"(a));
}
__device__ __forceinline__ ull neg2(ull a) { return a ^ 0x8000000080000000ULL; }

// ---------------------------------------------------------------------------
// Compile-time PGA(3,0,1) tables. Blade order matches the reference:
// idx : (), e0,e1,e2,e3, e01,e02,e03,e12,e13,e23, e012,e013,e023,e123, e0123
// ---------------------------------------------------------------------------
namespace ga {

__host__ __device__ constexpr unsigned bladeMask(int i) {
    constexpr unsigned m[16] = {0u,1u,2u,4u,8u, 3u,5u,9u,6u,10u,12u, 7u,11u,13u,14u, 15u};
    return m[i];
}
__host__ __device__ constexpr int idxOfMask(unsigned m) {
    constexpr int t[16] = {0,1,2,5,3,6,8,11,4,7,9,12,10,13,14,15};
    return t[m];
}
__host__ __device__ constexpr int invCnt(unsigned a, unsigned b) {
    int s = 0;
    for (int i = 0; i < 4; ++i)
        if ((b >> i) & 1u)
            for (int j = i + 1; j < 4; ++j)
                if ((a >> j) & 1u) ++s;
    return s;
}
__host__ __device__ constexpr float gpSign(int j, int k) {
    unsigned a = bladeMask(j), b = bladeMask(k);
    if (a & b & 1u) return 0.0f;                   // e0*e0 = 0
    return (invCnt(a, b) & 1) ? -1.0f : 1.0f;
}
__host__ __device__ constexpr int gpTgt(int j, int k) {
    return idxOfMask(bladeMask(j) ^ bladeMask(k));
}
__host__ __device__ constexpr float dSign(int t) {
    unsigned m = bladeMask(t);
    return (invCnt(m, 15u ^ m) & 1) ? -1.0f : 1.0f;
}
__host__ __device__ constexpr float jnCoef(int b, int c) {
    unsigned mb = bladeMask(b), mc = bladeMask(c);
    if ((mb | mc) != 15u) return 0.0f;
    unsigned ma = mb & mc;
    int ia = idxOfMask(15u ^ ma);
    unsigned cb = 15u ^ mb, cc = 15u ^ mc;
    float so = (invCnt(cb, cc) & 1) ? -1.0f : 1.0f;
    return dSign(ia) * so * dSign(b) * dSign(c);
}
__host__ __device__ constexpr int jnTgt(int b, int c) {
    return idxOfMask(bladeMask(b) & bladeMask(c));
}

template<int...> struct iseq {};
template<int N, int... S> struct mkseq : mkseq<N-1, N-1, S...> {};
template<int... S> struct mkseq<0, S...> { using type = iseq<S...>; };

template<int J, int K>
__device__ __forceinline__ void gpTerm(const ull (&L)[16], const ull (&nL)[16],
                                       const ull (&R)[16], ull (&h)[16]) {
    constexpr float s = gpSign(J, K);
    if constexpr (s > 0.5f) {
        constexpr int t = gpTgt(J, K);
        h[t] = fma2(L[J], R[K], h[t]);
    } else if constexpr (s < -0.5f) {
        constexpr int t = gpTgt(J, K);
        h[t] = fma2(nL[J], R[K], h[t]);
    }
}
template<int J, int... Ks>
__device__ __forceinline__ void gpRow(const ull (&L)[16], const ull (&nL)[16],
                                      const ull (&R)[16], ull (&h)[16], iseq<Ks...>) {
    (gpTerm<J, Ks>(L, nL, R, h), ...);
}
template<int... Js>
__device__ __forceinline__ void gpAll(const ull (&L)[16], const ull (&nL)[16],
                                      const ull (&R)[16], ull (&h)[16], iseq<Js...>) {
    (gpRow<Js>(L, nL, R, h, typename mkseq<16>::type{}), ...);
}

template<int J, int K>
__device__ __forceinline__ void jnTerm(const ull (&L)[16], const ull (&nL)[16],
                                       const ull (&R)[16], ull (&h)[16]) {
    constexpr float s = jnCoef(J, K);
    if constexpr (s > 0.5f) {
        constexpr int t = jnTgt(J, K);
        h[t] = fma2(L[J], R[K], h[t]);
    } else if constexpr (s < -0.5f) {
        constexpr int t = jnTgt(J, K);
        h[t] = fma2(nL[J], R[K], h[t]);
    }
}
template<int J, int... Ks>
__device__ __forceinline__ void jnRow(const ull (&L)[16], const ull (&nL)[16],
                                      const ull (&R)[16], ull (&h)[16], iseq<Ks...>) {
    (jnTerm<J, Ks>(L, nL, R, h), ...);
}
template<int... Js>
__device__ __forceinline__ void jnAll(const ull (&L)[16], const ull (&nL)[16],
                                      const ull (&R)[16], ull (&h)[16], iseq<Js...>) {
    (jnRow<Js>(L, nL, R, h, typename mkseq<16>::type{}), ...);
}

// Equivariant-linear accumulation (packed pair), one input channel.
// grades = [0,1,1,1,1, 2,2,2,2,2,2, 3,3,3,3, 4]
// e0 wedge (+1): 1<-0 (w5); 5,6,7<-2,3,4 (w6); 11,12,13<-8,9,10 (w7); 15<-14 (w8)
__device__ __forceinline__ void linAcc2(ull (&o)[16], const ull (&w)[9], const ull (&x)[16]) {
    o[0]  = fma2(w[0], x[0],  o[0]);
    o[1]  = fma2(w[1], x[1],  o[1]);  o[1]  = fma2(w[5], x[0],  o[1]);
    o[2]  = fma2(w[1], x[2],  o[2]);
    o[3]  = fma2(w[1], x[3],  o[3]);
    o[4]  = fma2(w[1], x[4],  o[4]);
    o[5]  = fma2(w[2], x[5],  o[5]);  o[5]  = fma2(w[6], x[2],  o[5]);
    o[6]  = fma2(w[2], x[6],  o[6]);  o[6]  = fma2(w[6], x[3],  o[6]);
    o[7]  = fma2(w[2], x[7],  o[7]);  o[7]  = fma2(w[6], x[4],  o[7]);
    o[8]  = fma2(w[2], x[8],  o[8]);
    o[9]  = fma2(w[2], x[9],  o[9]);
    o[10] = fma2(w[2], x[10], o[10]);
    o[11] = fma2(w[3], x[11], o[11]); o[11] = fma2(w[7], x[8],  o[11]);
    o[12] = fma2(w[3], x[12], o[12]); o[12] = fma2(w[7], x[9],  o[12]);
    o[13] = fma2(w[3], x[13], o[13]); o[13] = fma2(w[7], x[10], o[13]);
    o[14] = fma2(w[3], x[14], o[14]);
    o[15] = fma2(w[4], x[15], o[15]); o[15] = fma2(w[8], x[14], o[15]);
}

} // namespace ga

// ---------------------------------------------------------------------------
// Kernel: 4 tokens per warp (two packed pairs), weights read once per quad.
// ---------------------------------------------------------------------------
#define NW 8
#define NTHREADS (NW * 32)

// shared memory float offsets
#define OFF_WA    0        // [32 i][9 b][32 lane]
#define OFF_WB    9216
#define OFF_WO    18432    // [32 c][9 b][32 o]
#define OFF_SA    27648    // [64 s][32 lane]
#define OFF_SB    29696
#define OFF_S2MV  31744
#define OFF_WM1   33792    // [32 c][32 o]
#define OFF_WM2   34816
#define OFF_WS1   35840    // [64 s][32 o]
#define OFF_WS2   37888
#define OFF_STG   39936
// Per-warp staging: TWO buffers of 32 rows x 32 floats (XOR-swizzled
// ulonglong2 slots), each reused for pair-interleaved x THEN hidden.
#define STG_PER_WARP (2 * 32 * 32)         // 2048 floats
#define SMEM_FLOATS (OFF_STG + NW * STG_PER_WARP)
#define SMEM_BYTES  (SMEM_FLOATS * 4)      // 225,280 B

__global__ void __launch_bounds__(NTHREADS, 1)
gb_kernel(const float* __restrict__ mv,      // [ntok][32][16]
          const float* __restrict__ refmv,   // [ntok][16]
          const float* __restrict__ scal,    // [ntok][64]
          const float* __restrict__ wLmv, const float* __restrict__ wLs,
          const float* __restrict__ wRmv, const float* __restrict__ wRs,
          const float* __restrict__ wJLmv, const float* __restrict__ wJLs,
          const float* __restrict__ wJRmv, const float* __restrict__ wJRs,
          const float* __restrict__ wOmv,    // [32 o][32 c][9 b]
          const float* __restrict__ wS2mv,   // [32 o][64 s]
          const float* __restrict__ wMvs2s,  // [64 o][32 c]
          const float* __restrict__ wS2s,    // [64 o][64 s]
          float* __restrict__ out,           // [ntok][32][16]
          float* __restrict__ outS,          // [ntok][64]
          int ntok)
{
    extern __shared__ float sm[];
    float* WA   = sm + OFF_WA;
    float* WB   = sm + OFF_WB;
    float* WO   = sm + OFF_WO;
    float* SA   = sm + OFF_SA;
    float* SB   = sm + OFF_SB;
    float* S2MV = sm + OFF_S2MV;
    float* WM1  = sm + OFF_WM1;
    float* WM2  = sm + OFF_WM2;
    float* WS1  = sm + OFF_WS1;
    float* WS2  = sm + OFF_WS2;

    const int tid  = threadIdx.x;
    const int lane = tid & 31;
    const int wid  = tid >> 5;

    // ---- stage weights (lane-permuted) ----
    // lane<16: A=left[lane], B=right[lane];  lane>=16: A=jl[l-16], B=jr[l-16]
    for (int idx = tid; idx < 9216; idx += NTHREADS) {
        const int l   = idx & 31;
        const int off = idx >> 5;               // i*9+b
        WA[idx] = (l < 16) ? wLmv[l * 288 + off] : wJLmv[(l - 16) * 288 + off];
        WB[idx] = (l < 16) ? wRmv[l * 288 + off] : wJRmv[(l - 16) * 288 + off];
        WO[idx] = wOmv[l * 288 + off];
    }
    for (int idx = tid; idx < 2048; idx += NTHREADS) {
        const int l = idx & 31;
        const int s = idx >> 5;
        SA[idx]   = (l < 16) ? wLs[l * 64 + s] : wJLs[(l - 16) * 64 + s];
        SB[idx]   = (l < 16) ? wRs[l * 64 + s] : wJRs[(l - 16) * 64 + s];
        S2MV[idx] = wS2mv[l * 64 + s];
        WS1[idx]  = wS2s[l * 64 + s];
        WS2[idx]  = wS2s[(32 + l) * 64 + s];
    }
    for (int idx = tid; idx < 1024; idx += NTHREADS) {
        const int l = idx & 31;
        const int c = idx >> 5;
        WM1[idx] = wMvs2s[l * 32 + c];
        WM2[idx] = wMvs2s[(32 + l) * 32 + c];
    }
    __syncthreads();

    float* buf1 = sm + OFF_STG + wid * STG_PER_WARP; // pair1 staging (32x32, swizzled)
    float* buf2 = buf1 + 1024;                       // pair2 staging

    const int gw = blockIdx.x * NW + wid;
    const int nw = gridDim.x * NW;
    const int nquad = ntok >> 2;

    for (int q = gw; q < nquad; q += nw) {
        const int t0 = 4 * q;

        // ---- stage x for both pairs (pair-interleaved, swizzled rows) ----
        // Row i: logical ulonglong2 slot t holds blades (2t,2t+1) pairs;
        // physical slot = t ^ (i & 7).
        #pragma unroll
        for (int pp = 0; pp < 2; ++pp) {
            const float4* gxA = reinterpret_cast<const float4*>(mv + (size_t)(t0 + 2*pp)     * 512);
            const float4* gxB = reinterpret_cast<const float4*>(mv + (size_t)(t0 + 2*pp + 1) * 512);
            float* buf = pp ? buf2 : buf1;
            #pragma unroll
            for (int it = 0; it < 4; ++it) {
                const int c = it * 32 + lane;    // chunk 0..127
                const int i = c >> 2, qq = c & 3;
                const float4 a = gxA[c];
                const float4 b = gxB[c];
                const int m  = i & 7;
                const int p0 = (2 * qq) ^ m;
                const int p1 = p0 ^ 1;
                float* base = buf + i * 32;
                *reinterpret_cast<float4*>(base + p0 * 4) = make_float4(a.x, b.x, a.y, b.y);
                *reinterpret_cast<float4*>(base + p1 * 4) = make_float4(a.z, b.z, a.w, b.w);
            }
        }
        __syncwarp();

        // ---- scalar-head pass: weights read ONCE, applied to all 4 tokens ----
        // Accumulates A0/B0 (input-linear blade 0), O0 (out-mv blade 0),
        // os1/os2 (scalar outputs), per token, as plain fp32.
        float A0[4], B0[4], O0[4], s1[4], s2[4];
        #pragma unroll
        for (int t = 0; t < 4; ++t) { A0[t]=0.f; B0[t]=0.f; O0[t]=0.f; s1[t]=0.f; s2[t]=0.f; }

        #pragma unroll 4
        for (int s4 = 0; s4 < 16; ++s4) {
            float4 sv[4];
            #pragma unroll
            for (int t = 0; t < 4; ++t)
                sv[t] = __ldg(reinterpret_cast<const float4*>(scal + (size_t)(t0 + t) * 64) + s4);
            #pragma unroll
            for (int k = 0; k < 4; ++k) {
                const int s = s4 * 4 + k;
                const float wsa = SA[s * 32 + lane];
                const float wsb = SB[s * 32 + lane];
                const float wo0 = S2MV[s * 32 + lane];
                const float w1  = WS1[s * 32 + lane];
                const float w2  = WS2[s * 32 + lane];
                #pragma unroll
                for (int t = 0; t < 4; ++t) {
                    const float x = (k == 0) ? sv[t].x : (k == 1) ? sv[t].y
                                   : (k == 2) ? sv[t].z : sv[t].w;
                    A0[t] = fmaf(wsa, x, A0[t]);
                    B0[t] = fmaf(wsb, x, B0[t]);
                    O0[t] = fmaf(wo0, x, O0[t]);
                    s1[t] = fmaf(w1,  x, s1[t]);
                    s2[t] = fmaf(w2,  x, s2[t]);
                }
            }
        }

        // ---- input equi-linears: weights read once per i, both pairs ----
        ull A1[16], B1[16], A2[16], B2[16];
        #pragma unroll
        for (int j = 0; j < 16; ++j) { A1[j]=0ULL; B1[j]=0ULL; A2[j]=0ULL; B2[j]=0ULL; }
        A1[0] = pack2(A0[0], A0[1]);  B1[0] = pack2(B0[0], B0[1]);
        A2[0] = pack2(A0[2], A0[3]);  B2[0] = pack2(B0[2], B0[3]);

        for (int i0 = 0; i0 < 32; i0 += 8) {
            #pragma unroll
            for (int k = 0; k < 8; ++k) {
                const int i = i0 + k;
                ull wa[9], wb[9];
                #pragma unroll
                for (int b = 0; b < 9; ++b) {
                    wa[b] = dup2(WA[(i * 9 + b) * 32 + lane]);
                    wb[b] = dup2(WB[(i * 9 + b) * 32 + lane]);
                }
                {
                    ull xr[16];
                    const float* base = buf1 + i * 32;
                    #pragma unroll
                    for (int t = 0; t < 8; ++t) {
                        const ulonglong2 v =
                            *reinterpret_cast<const ulonglong2*>(base + ((t ^ k) * 4));
                        xr[2*t] = v.x; xr[2*t+1] = v.y;
                    }
                    ga::linAcc2(A1, wa, xr);
                    ga::linAcc2(B1, wb, xr);
                }
                {
                    ull xr[16];
                    const float* base = buf2 + i * 32;
                    #pragma unroll
                    for (int t = 0; t < 8; ++t) {
                        const ulonglong2 v =
                            *reinterpret_cast<const ulonglong2*>(base + ((t ^ k) * 4));
                        xr[2*t] = v.x; xr[2*t+1] = v.y;
                    }
                    ga::linAcc2(A2, wa, xr);
                    ga::linAcc2(B2, wb, xr);
                }
            }
        }
        __syncwarp();   // all lanes done reading x staging

        // ---- bilinear (gp lanes 0..15, join lanes 16..31), both pairs ----
        const ull refp1 = pack2(refmv[(size_t)(t0)     * 16 + 15],
                                refmv[(size_t)(t0 + 1) * 16 + 15]);
        const ull refp2 = pack2(refmv[(size_t)(t0 + 2) * 16 + 15],
                                refmv[(size_t)(t0 + 3) * 16 + 15]);
        #pragma unroll
        for (int pp = 0; pp < 2; ++pp) {
            const ull* Ap = pp ? A2 : A1;
            const ull* Bp = pp ? B2 : B1;
            const ull refp = pp ? refp2 : refp1;
            float* buf = pp ? buf2 : buf1;
            ull h[16];
            #pragma unroll
            for (int j = 0; j < 16; ++j) h[j] = 0ULL;
            ull Av[16], nA[16], Bv[16];
            #pragma unroll
            for (int j = 0; j < 16; ++j) { Av[j] = Ap[j]; nA[j] = neg2(Ap[j]); Bv[j] = Bp[j]; }
            if (lane < 16) {
                ga::gpAll(Av, nA, Bv, h, typename ga::mkseq<16>::type{});
            } else {
                ga::jnAll(Av, nA, Bv, h, typename ga::mkseq<16>::type{});
                #pragma unroll
                for (int j = 0; j < 16; ++j) h[j] = mul2(h[j], refp);
            }
            // stage hidden (lane = channel) into the same buffer, swizzled
            float* base = buf + lane * 32;
            const int m = lane & 7;
            #pragma unroll
            for (int t = 0; t < 8; ++t)
                *reinterpret_cast<ulonglong2*>(base + ((t ^ m) * 4)) =
                    make_ulonglong2(h[2*t], h[2*t+1]);
        }
        __syncwarp();

        // ---- output equi-linear + scalar heads: weights once, both pairs ----
        ull O1[16], O2[16];
        O1[0] = pack2(O0[0], O0[1]);
        O2[0] = pack2(O0[2], O0[3]);
        #pragma unroll
        for (int j = 1; j < 16; ++j) { O1[j] = 0ULL; O2[j] = 0ULL; }
        ull os1p1 = pack2(s1[0], s1[1]), os2p1 = pack2(s2[0], s2[1]);
        ull os1p2 = pack2(s1[2], s1[3]), os2p2 = pack2(s2[2], s2[3]);

        for (int c0 = 0; c0 < 32; c0 += 8) {
            #pragma unroll
            for (int k = 0; k < 8; ++k) {
                const int c = c0 + k;
                ull wo[9];
                #pragma unroll
                for (int b = 0; b < 9; ++b) wo[b] = dup2(WO[(c * 9 + b) * 32 + lane]);
                const ull wm1 = dup2(WM1[c * 32 + lane]);
                const ull wm2 = dup2(WM2[c * 32 + lane]);
                {
                    ull hr[16];
                    const float* base = buf1 + c * 32;
                    #pragma unroll
                    for (int t = 0; t < 8; ++t) {
                        const ulonglong2 v =
                            *reinterpret_cast<const ulonglong2*>(base + ((t ^ k) * 4));
                        hr[2*t] = v.x; hr[2*t+1] = v.y;
                    }
                    ga::linAcc2(O1, wo, hr);
                    os1p1 = fma2(wm1, hr[0], os1p1);
                    os2p1 = fma2(wm2, hr[0], os2p1);
                }
                {
                    ull hr[16];
                    const float* base = buf2 + c * 32;
                    #pragma unroll
                    for (int t = 0; t < 8; ++t) {
                        const ulonglong2 v =
                            *reinterpret_cast<const ulonglong2*>(base + ((t ^ k) * 4));
                        hr[2*t] = v.x; hr[2*t+1] = v.y;
                    }
                    ga::linAcc2(O2, wo, hr);
                    os1p2 = fma2(wm1, hr[0], os1p2);
                    os2p2 = fma2(wm2, hr[0], os2p2);
                }
            }
        }

        // ---- write outputs ----
        #pragma unroll
        for (int pp = 0; pp < 2; ++pp) {
            const ull* Op = pp ? O2 : O1;
            float Oa[16], Ob[16];
            #pragma unroll
            for (int j = 0; j < 16; ++j) unpack2(Op[j], Oa[j], Ob[j]);
            float* omA = out + (size_t)(t0 + 2*pp)     * 512 + lane * 16;
            float* omB = out + (size_t)(t0 + 2*pp + 1) * 512 + lane * 16;
            #pragma unroll
            for (int m = 0; m < 4; ++m) {
                *reinterpret_cast<float4*>(omA + m * 4) =
                    make_float4(Oa[m*4+0], Oa[m*4+1], Oa[m*4+2], Oa[m*4+3]);
                *reinterpret_cast<float4*>(omB + m * 4) =
                    make_float4(Ob[m*4+0], Ob[m*4+1], Ob[m*4+2], Ob[m*4+3]);
            }
        }
        {
            float a1, b1, a2, b2;
            unpack2(os1p1, a1, b1); unpack2(os2p1, a2, b2);
            outS[(size_t)(t0)     * 64 + lane]      = a1;
            outS[(size_t)(t0)     * 64 + 32 + lane] = a2;
            outS[(size_t)(t0 + 1) * 64 + lane]      = b1;
            outS[(size_t)(t0 + 1) * 64 + 32 + lane] = b2;
            unpack2(os1p2, a1, b1); unpack2(os2p2, a2, b2);
            outS[(size_t)(t0 + 2) * 64 + lane]      = a1;
            outS[(size_t)(t0 + 2) * 64 + 32 + lane] = a2;
            outS[(size_t)(t0 + 3) * 64 + lane]      = b1;
            outS[(size_t)(t0 + 3) * 64 + 32 + lane] = b2;
        }
        __syncwarp();   // staging reused next iteration
    }
}

// ---------------------------------------------------------------------------
// Launch
// ---------------------------------------------------------------------------
extern "C" void kernel_launch(void* const* d_in, const int* in_sizes, int n_in,
                              void* d_out, int out_size) {
    const float* mv     = (const float*)d_in[0];
    const float* refmv  = (const float*)d_in[1];
    const float* scal   = (const float*)d_in[2];
    // d_in[3..5] = basis, gp, jn (structure hardcoded at compile time)
    const float* wLmv   = (const float*)d_in[6];
    const float* wLs    = (const float*)d_in[7];
    const float* wRmv   = (const float*)d_in[8];
    const float* wRs    = (const float*)d_in[9];
    const float* wJLmv  = (const float*)d_in[10];
    const float* wJLs   = (const float*)d_in[11];
    const float* wJRmv  = (const float*)d_in[12];
    const float* wJRs   = (const float*)d_in[13];
    const float* wOmv   = (const float*)d_in[14];
    const float* wS2mv  = (const float*)d_in[15];
    const float* wMvs2s = (const float*)d_in[16];
    const float* wS2s   = (const float*)d_in[17];

    const int ntok = in_sizes[0] / 512;          // 32768
    float* out  = (float*)d_out;                 // [ntok*512] out_mv
    float* outS = out + (size_t)ntok * 512;      // [ntok*64]  out_s

    int dev = 0;
    cudaGetDevice(&dev);
    int nsm = 148;
    cudaDeviceGetAttribute(&nsm, cudaDevAttrMultiProcessorCount, dev);

    cudaFuncSetAttribute(gb_kernel, cudaFuncAttributeMaxDynamicSharedMemorySize, SMEM_BYTES);

    gb_kernel<<<nsm, NTHREADS, SMEM_BYTES>>>(
        mv, refmv, scal,
        wLmv, wLs, wRmv, wRs, wJLmv, wJLs, wJRmv, wJRs,
        wOmv, wS2mv, wMvs2s, wS2s,
        out, outS, ntok);
}